// round 1
// baseline (speedup 1.0000x reference)
#include <cuda_runtime.h>

#define Bsz  256
#define Tlen 2048
#define Idim 128
#define Hdim 64
#define Gdim 256                       // 4*H
#define Mrows (Bsz * Tlen)             // 524288

// Scratch (static device arrays: allocation-free per harness rules)
__device__ float g_pre[(size_t)Mrows * Gdim];   // 512 MiB: pre-activations for current layer
__device__ float g_h0 [(size_t)Mrows * Hdim];   // 128 MiB: layer output ping
__device__ float g_h1 [(size_t)Mrows * Hdim];   // 128 MiB: layer output pong

__device__ __forceinline__ float sigm_f(float x) {
    return 1.0f / (1.0f + __expf(-x));
}
__device__ __forceinline__ float tanh_f(float x) {
    return 2.0f / (1.0f + __expf(-2.0f * x)) - 1.0f;
}

// ---------------------------------------------------------------------------
// GEMM: g_pre[m, n] = sum_k A[m, k] * W[n, k] + b_ih[n] + b_hh[n]
// A: [Mrows, K] row-major (x, g_h0, or g_h1 selected by `sel`)
// W: [256, K] row-major
// Tile 64(M) x 64(N), 256 threads, 4x4 microtile per thread, K-chunks of 16.
// ---------------------------------------------------------------------------
__global__ __launch_bounds__(256) void gemm_pre_kernel(
    const float* __restrict__ Aext, int sel,
    const float* __restrict__ W,
    const float* __restrict__ bih, const float* __restrict__ bhh,
    int K)
{
    const float* A = (sel == 0) ? Aext : ((sel == 1) ? g_h0 : g_h1);

    __shared__ float As[16][68];   // [k][m], pad 4 to keep float4 alignment + spread banks
    __shared__ float Ws[16][68];   // [k][n]

    const int t  = threadIdx.x;
    const int tx = t & 15;         // n-micro position
    const int ty = t >> 4;         // m-micro position
    const long m0 = (long)blockIdx.y * 64;
    const int  n0 = blockIdx.x * 64;

    float acc[4][4];
#pragma unroll
    for (int r = 0; r < 4; r++)
#pragma unroll
        for (int c = 0; c < 4; c++) acc[r][c] = 0.0f;

    const int kk = t & 15;         // k within chunk (fast index -> coalesced gmem)
    const int mm = t >> 4;         // row group

    for (int k0 = 0; k0 < K; k0 += 16) {
#pragma unroll
        for (int r = 0; r < 4; r++)
            As[kk][mm + 16 * r] = A[(m0 + mm + 16 * r) * K + k0 + kk];
#pragma unroll
        for (int r = 0; r < 4; r++)
            Ws[kk][mm + 16 * r] = W[(size_t)(n0 + mm + 16 * r) * K + k0 + kk];
        __syncthreads();

#pragma unroll
        for (int q = 0; q < 16; q++) {
            float4 a = *(const float4*)&As[q][ty * 4];
            float4 b = *(const float4*)&Ws[q][tx * 4];
            acc[0][0] += a.x * b.x; acc[0][1] += a.x * b.y;
            acc[0][2] += a.x * b.z; acc[0][3] += a.x * b.w;
            acc[1][0] += a.y * b.x; acc[1][1] += a.y * b.y;
            acc[1][2] += a.y * b.z; acc[1][3] += a.y * b.w;
            acc[2][0] += a.z * b.x; acc[2][1] += a.z * b.y;
            acc[2][2] += a.z * b.z; acc[2][3] += a.z * b.w;
            acc[3][0] += a.w * b.x; acc[3][1] += a.w * b.y;
            acc[3][2] += a.w * b.z; acc[3][3] += a.w * b.w;
        }
        __syncthreads();
    }

    float bias[4];
#pragma unroll
    for (int c = 0; c < 4; c++) {
        int n = n0 + tx * 4 + c;
        bias[c] = bih[n] + bhh[n];
    }
#pragma unroll
    for (int r = 0; r < 4; r++) {
        float4 o;
        o.x = acc[r][0] + bias[0];
        o.y = acc[r][1] + bias[1];
        o.z = acc[r][2] + bias[2];
        o.w = acc[r][3] + bias[3];
        *(float4*)&g_pre[(size_t)(m0 + ty * 4 + r) * Gdim + n0 + tx * 4] = o;
    }
}

// ---------------------------------------------------------------------------
// Recurrent layer: one block per batch element, 256 threads (thread g = gate g).
// w_hh row of each gate held in 64 registers; h kept in shared memory.
// MODE 0 -> write h sequence to g_h0; MODE 1 -> g_h1;
// MODE 2 -> last layer: fuse FC head (warp-0 reduction) into `out`.
// ---------------------------------------------------------------------------
template <int MODE>
__global__ __launch_bounds__(256, 2) void lstm_rec_kernel(
    const float* __restrict__ w_hh,
    const float* __restrict__ fc_w, const float* __restrict__ fc_b,
    float* __restrict__ out)
{
    __shared__ float h_s[64];
    __shared__ float gate_s[256];

    const int g = threadIdx.x;
    const int b = blockIdx.x;

    float wreg[64];
#pragma unroll
    for (int k = 0; k < 64; k++) wreg[k] = w_hh[(size_t)g * 64 + k];

    float c = 0.0f;
    if (g < 64) h_s[g] = 0.0f;

    float fwa = 0.0f, fwb = 0.0f, fcb = 0.0f;
    if (MODE == 2 && g < 32) {
        fwa = fc_w[g];
        fwb = fc_w[g + 32];
        fcb = fc_b[0];
    }
    __syncthreads();

    const float* pre = g_pre + (size_t)b * Tlen * Gdim + g;
    float* hout = (MODE == 0) ? g_h0 : g_h1;

    float pnext = pre[0];

    for (int t = 0; t < Tlen; t++) {
        float pval = pnext;
        if (t + 1 < Tlen) pnext = pre[(size_t)(t + 1) * Gdim];   // prefetch 1 step ahead

        // gate pre-activation: pval + sum_k h[k] * w_hh[g][k]
        float s0 = 0.0f, s1 = 0.0f, s2 = 0.0f, s3 = 0.0f;
        const float4* h4 = (const float4*)h_s;
#pragma unroll
        for (int q = 0; q < 16; q++) {
            float4 hv = h4[q];
            s0 += wreg[4 * q + 0] * hv.x;
            s1 += wreg[4 * q + 1] * hv.y;
            s2 += wreg[4 * q + 2] * hv.z;
            s3 += wreg[4 * q + 3] * hv.w;
        }
        float a = pval + ((s0 + s1) + (s2 + s3));

        // i: [0,64) f: [64,128) g: [128,192) o: [192,256)  (warp-uniform branch)
        float v = (g < 128 || g >= 192) ? sigm_f(a) : tanh_f(a);
        gate_s[g] = v;
        __syncthreads();

        if (g < 64) {
            float iv = gate_s[g];
            float fv = gate_s[64 + g];
            float gv = gate_s[128 + g];
            float ov = gate_s[192 + g];
            c = fv * c + iv * gv;
            float h = ov * tanh_f(c);
            h_s[g] = h;
            if (MODE < 2)
                hout[((size_t)b * Tlen + t) * Hdim + g] = h;
        }
        __syncthreads();

        if (MODE == 2 && g < 32) {       // fused FC head on warp 0
            float s = h_s[g] * fwa + h_s[g + 32] * fwb;
            s += __shfl_down_sync(0xffffffffu, s, 16);
            s += __shfl_down_sync(0xffffffffu, s, 8);
            s += __shfl_down_sync(0xffffffffu, s, 4);
            s += __shfl_down_sync(0xffffffffu, s, 2);
            s += __shfl_down_sync(0xffffffffu, s, 1);
            if (g == 0) out[(size_t)b * Tlen + t] = s + fcb;
        }
    }
}

extern "C" void kernel_launch(void* const* d_in, const int* in_sizes, int n_in,
                              void* d_out, int out_size)
{
    const float* x    = (const float*)d_in[0];
    const float* wih0 = (const float*)d_in[1];
    const float* whh0 = (const float*)d_in[2];
    const float* bih0 = (const float*)d_in[3];
    const float* bhh0 = (const float*)d_in[4];
    const float* wih1 = (const float*)d_in[5];
    const float* whh1 = (const float*)d_in[6];
    const float* bih1 = (const float*)d_in[7];
    const float* bhh1 = (const float*)d_in[8];
    const float* wih2 = (const float*)d_in[9];
    const float* whh2 = (const float*)d_in[10];
    const float* bih2 = (const float*)d_in[11];
    const float* bhh2 = (const float*)d_in[12];
    const float* fcw  = (const float*)d_in[13];
    const float* fcb  = (const float*)d_in[14];
    float* out = (float*)d_out;

    dim3 ggrid(Gdim / 64, Mrows / 64);   // (4, 8192)

    // Layer 0
    gemm_pre_kernel<<<ggrid, 256>>>(x, 0, wih0, bih0, bhh0, Idim);
    lstm_rec_kernel<0><<<Bsz, 256>>>(whh0, nullptr, nullptr, nullptr);
    // Layer 1
    gemm_pre_kernel<<<ggrid, 256>>>(nullptr, 1, wih1, bih1, bhh1, Hdim);
    lstm_rec_kernel<1><<<Bsz, 256>>>(whh1, nullptr, nullptr, nullptr);
    // Layer 2 + fused FC head
    gemm_pre_kernel<<<ggrid, 256>>>(nullptr, 2, wih2, bih2, bhh2, Hdim);
    lstm_rec_kernel<2><<<Bsz, 256>>>(whh2, fcw, fcb, out);
}

// round 8
// speedup vs baseline: 1.0381x; 1.0381x over previous
#include <cuda_runtime.h>
#include <cuda_bf16.h>
#include <cstdint>

#define Bsz  256
#define Tlen 2048
#define Idim 128
#define Hdim 64
#define Gdim 256                       // 4*H
#define Mrows (Bsz * Tlen)             // 524288

// Scratch (static device arrays: allocation-free per harness rules)
__device__ float g_pre[(size_t)Mrows * Gdim];   // 512 MiB: pre-activations
__device__ float g_h0 [(size_t)Mrows * Hdim];   // 128 MiB: layer output ping
__device__ float g_h1 [(size_t)Mrows * Hdim];   // 128 MiB: layer output pong

__device__ __forceinline__ float sigm_f(float x) {
    return 1.0f / (1.0f + __expf(-x));
}
__device__ __forceinline__ float tanh_f(float x) {
    return 2.0f / (1.0f + __expf(-2.0f * x)) - 1.0f;
}

// ---------------------------------------------------------------------------
// mma.sync helpers (baseline PTX — works on plain sm_103 target)
// ---------------------------------------------------------------------------
__device__ __forceinline__ void ldsm_x4(uint32_t* r, uint32_t addr) {
    asm volatile("ldmatrix.sync.aligned.m8n8.x4.shared.b16 {%0,%1,%2,%3}, [%4];"
                 : "=r"(r[0]), "=r"(r[1]), "=r"(r[2]), "=r"(r[3]) : "r"(addr));
}
__device__ __forceinline__ void mma16816(float* d, const uint32_t* a, const uint32_t* b) {
    asm volatile(
        "mma.sync.aligned.m16n8k16.row.col.f32.bf16.bf16.f32 "
        "{%0,%1,%2,%3}, {%4,%5,%6,%7}, {%8,%9}, {%0,%1,%2,%3};"
        : "+f"(d[0]), "+f"(d[1]), "+f"(d[2]), "+f"(d[3])
        : "r"(a[0]), "r"(a[1]), "r"(a[2]), "r"(a[3]), "r"(b[0]), "r"(b[1]));
}

// ===========================================================================
// GEMM: g_pre[m, n] = sum_k A[m,k]*W[n,k] + bih[n] + bhh[n]
// Block tile M=64 x N=256 (full N), K-chunks of 32, split-bf16 3-term.
// A fp32 [Mrows, K] (x / g_h0 / g_h1 via sel); W fp32 [256, K].
// In-kernel fp32->bf16 hi/lo conversion (each A elem converted exactly once).
// smem (dynamic): A_hi[64][40] | A_lo[64][40] | W_hi[256][40] | W_lo[256][40]
// ===========================================================================
#define SMA_HI 0
#define SMA_LO 5120
#define SMW_HI 10240
#define SMW_LO 30720
#define GSM_TOTAL 51200

__global__ __launch_bounds__(256, 2) void gemm_mma_kernel(
    const float* __restrict__ Aext, int sel,
    const float* __restrict__ W,
    const float* __restrict__ bih, const float* __restrict__ bhh,
    int K)
{
    extern __shared__ char smem[];
    const uint32_t sbase = (uint32_t)__cvta_generic_to_shared(smem);

    const float* A = (sel == 0) ? Aext : ((sel == 1) ? g_h0 : g_h1);

    const int t   = threadIdx.x;
    const int wid = t >> 5;
    const int lid = t & 31;
    const int wm  = wid >> 2;          // 0..1 : warp row   (32 M each)
    const int wn  = wid & 3;           // 0..3 : warp col   (64 N each)
    const size_t m0 = (size_t)blockIdx.x * 64;

    float acc[2][8][4];
#pragma unroll
    for (int i = 0; i < 2; i++)
#pragma unroll
        for (int j = 0; j < 8; j++)
#pragma unroll
            for (int v = 0; v < 4; v++) acc[i][j][v] = 0.0f;

    // per-lane ldmatrix address components (stride 40 bf16 = 80B per row)
    const int rowA = wm * 32 + (lid & 7) + ((lid >> 3) & 1) * 8;
    const int colA = (lid >> 4) * 8;
    const int rowB = wn * 64 + (lid >> 4) * 8 + (lid & 7);
    const int colB = ((lid >> 3) & 1) * 8;

    const int nchunks = K >> 5;
    for (int c = 0; c < nchunks; c++) {
        const int k0 = c << 5;

        // ---- load + split-convert A tile (64 x 32): 512 float4, 2/thread ----
#pragma unroll
        for (int i = 0; i < 2; i++) {
            int f   = t + i * 256;
            int row = f >> 3;
            int c4  = (f & 7) << 2;
            float4 v = *(const float4*)&A[(m0 + row) * K + k0 + c4];
            __nv_bfloat162 h0 = __floats2bfloat162_rn(v.x, v.y);
            __nv_bfloat162 h1 = __floats2bfloat162_rn(v.z, v.w);
            __nv_bfloat162 l0 = __floats2bfloat162_rn(v.x - __bfloat162float(h0.x),
                                                      v.y - __bfloat162float(h0.y));
            __nv_bfloat162 l1 = __floats2bfloat162_rn(v.z - __bfloat162float(h1.x),
                                                      v.w - __bfloat162float(h1.y));
            uint32_t off = (uint32_t)(row * 40 + c4) * 2;
            *(uint2*)(smem + SMA_HI + off) =
                make_uint2(*(uint32_t*)&h0, *(uint32_t*)&h1);
            *(uint2*)(smem + SMA_LO + off) =
                make_uint2(*(uint32_t*)&l0, *(uint32_t*)&l1);
        }
        // ---- load + split-convert W tile (256 x 32): 2048 float4, 8/thread ----
#pragma unroll
        for (int i = 0; i < 8; i++) {
            int f   = t + i * 256;
            int row = f >> 3;
            int c4  = (f & 7) << 2;
            float4 v = *(const float4*)&W[(size_t)row * K + k0 + c4];
            __nv_bfloat162 h0 = __floats2bfloat162_rn(v.x, v.y);
            __nv_bfloat162 h1 = __floats2bfloat162_rn(v.z, v.w);
            __nv_bfloat162 l0 = __floats2bfloat162_rn(v.x - __bfloat162float(h0.x),
                                                      v.y - __bfloat162float(h0.y));
            __nv_bfloat162 l1 = __floats2bfloat162_rn(v.z - __bfloat162float(h1.x),
                                                      v.w - __bfloat162float(h1.y));
            uint32_t off = (uint32_t)(row * 40 + c4) * 2;
            *(uint2*)(smem + SMW_HI + off) =
                make_uint2(*(uint32_t*)&h0, *(uint32_t*)&h1);
            *(uint2*)(smem + SMW_LO + off) =
                make_uint2(*(uint32_t*)&l0, *(uint32_t*)&l1);
        }
        __syncthreads();

        // ---- mma over the 32-deep chunk (2 k16 steps, 3 precision terms) ----
#pragma unroll
        for (int kt = 0; kt < 2; kt++) {
            uint32_t afh[2][4], afl[2][4];
#pragma unroll
            for (int mt = 0; mt < 2; mt++) {
                uint32_t ao = (uint32_t)((rowA + mt * 16) * 40 + colA + kt * 16) * 2;
                ldsm_x4(afh[mt], sbase + SMA_HI + ao);
                ldsm_x4(afl[mt], sbase + SMA_LO + ao);
            }
#pragma unroll
            for (int nt2 = 0; nt2 < 4; nt2++) {
                uint32_t bo = (uint32_t)((rowB + nt2 * 16) * 40 + colB + kt * 16) * 2;
                uint32_t bfh[4], bfl[4];
                ldsm_x4(bfh, sbase + SMW_HI + bo);
                ldsm_x4(bfl, sbase + SMW_LO + bo);
#pragma unroll
                for (int mt = 0; mt < 2; mt++)
#pragma unroll
                    for (int half = 0; half < 2; half++) {
                        int nt = nt2 * 2 + half;
                        mma16816(acc[mt][nt], afh[mt], &bfh[half * 2]);  // hi*hi
                        mma16816(acc[mt][nt], afh[mt], &bfl[half * 2]);  // hi*lo
                        mma16816(acc[mt][nt], afl[mt], &bfh[half * 2]);  // lo*hi
                    }
            }
        }
        __syncthreads();
    }

    // ---- epilogue: d[row, n] + bias ----
    const int g  = lid >> 2;
    const int tg = lid & 3;
#pragma unroll
    for (int nt = 0; nt < 8; nt++) {
        int n = wn * 64 + nt * 8 + tg * 2;
        float b0 = bih[n]     + bhh[n];
        float b1 = bih[n + 1] + bhh[n + 1];
        size_t row0 = m0 + wm * 32 + g;
#pragma unroll
        for (int mt = 0; mt < 2; mt++) {
            size_t r0 = row0 + mt * 16;
            float2 o0 = make_float2(acc[mt][nt][0] + b0, acc[mt][nt][1] + b1);
            float2 o1 = make_float2(acc[mt][nt][2] + b0, acc[mt][nt][3] + b1);
            *(float2*)&g_pre[r0 * Gdim + n]       = o0;
            *(float2*)&g_pre[(r0 + 8) * Gdim + n] = o1;
        }
    }
}

// ===========================================================================
// Recurrent layer: one block per TWO batch elements (grid=128 -> single wave).
// Thread g computes gate g for both batches; w_hh row in 64 registers.
// MODE 0 -> g_h0; MODE 1 -> g_h1; MODE 2 -> fused FC head into out.
// ===========================================================================
template <int MODE>
__global__ __launch_bounds__(256) void lstm_rec_kernel(
    const float* __restrict__ w_hh,
    const float* __restrict__ fc_w, const float* __restrict__ fc_b,
    float* __restrict__ out)
{
    __shared__ __align__(16) float h_s[2][64];
    __shared__ float gate_s[2][256];

    const int g = threadIdx.x;
    const int b2 = blockIdx.x;           // handles batches 2*b2, 2*b2+1

    float wreg[64];
#pragma unroll
    for (int k = 0; k < 64; k++) wreg[k] = w_hh[(size_t)g * 64 + k];

    float c = 0.0f;                       // cell state for (batch g>>6, unit g&63)
    if (g < 128) h_s[g >> 6][g & 63] = 0.0f;

    float fwa = 0.0f, fwb = 0.0f, fcb = 0.0f;
    if (MODE == 2 && g < 64) {
        fwa = fc_w[g & 31];
        fwb = fc_w[(g & 31) + 32];
        fcb = fc_b[0];
    }
    __syncthreads();

    const float* pre0 = g_pre + ((size_t)(2 * b2)     * Tlen) * Gdim + g;
    const float* pre1 = g_pre + ((size_t)(2 * b2 + 1) * Tlen) * Gdim + g;
    float* hout = (MODE == 0) ? g_h0 : g_h1;

    float pn0 = pre0[0];
    float pn1 = pre1[0];

    for (int t = 0; t < Tlen; t++) {
        float pv0 = pn0, pv1 = pn1;
        if (t + 1 < Tlen) {
            pn0 = pre0[(size_t)(t + 1) * Gdim];
            pn1 = pre1[(size_t)(t + 1) * Gdim];
        }

        float a0 = 0.0f, a1 = 0.0f, b0 = 0.0f, b1 = 0.0f;
        const float4* h40 = (const float4*)h_s[0];
        const float4* h41 = (const float4*)h_s[1];
#pragma unroll
        for (int q = 0; q < 16; q++) {
            float4 hv0 = h40[q];
            float4 hv1 = h41[q];
            a0 += wreg[4 * q + 0] * hv0.x;  a1 += wreg[4 * q + 0] * hv1.x;
            b0 += wreg[4 * q + 1] * hv0.y;  b1 += wreg[4 * q + 1] * hv1.y;
            a0 += wreg[4 * q + 2] * hv0.z;  a1 += wreg[4 * q + 2] * hv1.z;
            b0 += wreg[4 * q + 3] * hv0.w;  b1 += wreg[4 * q + 3] * hv1.w;
        }
        float s0 = pv0 + (a0 + b0);
        float s1 = pv1 + (a1 + b1);

        // i:[0,64) f:[64,128) g:[128,192) o:[192,256)  (warp-uniform branch)
        float v0, v1;
        if (g < 128 || g >= 192) { v0 = sigm_f(s0); v1 = sigm_f(s1); }
        else                     { v0 = tanh_f(s0); v1 = tanh_f(s1); }
        gate_s[0][g] = v0;
        gate_s[1][g] = v1;
        __syncthreads();

        if (g < 128) {
            int bb = g >> 6, u = g & 63;
            float iv = gate_s[bb][u];
            float fv = gate_s[bb][64 + u];
            float gv = gate_s[bb][128 + u];
            float ov = gate_s[bb][192 + u];
            c = fv * c + iv * gv;
            float h = ov * tanh_f(c);
            h_s[bb][u] = h;
            if (MODE < 2)
                hout[((size_t)(2 * b2 + bb) * Tlen + t) * Hdim + u] = h;
        }
        __syncthreads();

        if (MODE == 2 && g < 64) {        // warps 0,1 -> batch 0,1 FC reductions
            int wb = g >> 5, l = g & 31;
            float s = h_s[wb][l] * fwa + h_s[wb][l + 32] * fwb;
            s += __shfl_down_sync(0xffffffffu, s, 16);
            s += __shfl_down_sync(0xffffffffu, s, 8);
            s += __shfl_down_sync(0xffffffffu, s, 4);
            s += __shfl_down_sync(0xffffffffu, s, 2);
            s += __shfl_down_sync(0xffffffffu, s, 1);
            if (l == 0) out[(size_t)(2 * b2 + wb) * Tlen + t] = s + fcb;
        }
    }
}

extern "C" void kernel_launch(void* const* d_in, const int* in_sizes, int n_in,
                              void* d_out, int out_size)
{
    const float* x    = (const float*)d_in[0];
    const float* wih0 = (const float*)d_in[1];
    const float* whh0 = (const float*)d_in[2];
    const float* bih0 = (const float*)d_in[3];
    const float* bhh0 = (const float*)d_in[4];
    const float* wih1 = (const float*)d_in[5];
    const float* whh1 = (const float*)d_in[6];
    const float* bih1 = (const float*)d_in[7];
    const float* bhh1 = (const float*)d_in[8];
    const float* wih2 = (const float*)d_in[9];
    const float* whh2 = (const float*)d_in[10];
    const float* bih2 = (const float*)d_in[11];
    const float* bhh2 = (const float*)d_in[12];
    const float* fcw  = (const float*)d_in[13];
    const float* fcb  = (const float*)d_in[14];
    float* out = (float*)d_out;

    cudaFuncSetAttribute(gemm_mma_kernel,
                         cudaFuncAttributeMaxDynamicSharedMemorySize, GSM_TOTAL);

    const int gblocks = Mrows / 64;     // 8192

    // Layer 0
    gemm_mma_kernel<<<gblocks, 256, GSM_TOTAL>>>(x, 0, wih0, bih0, bhh0, Idim);
    lstm_rec_kernel<0><<<Bsz / 2, 256>>>(whh0, nullptr, nullptr, nullptr);
    // Layer 1
    gemm_mma_kernel<<<gblocks, 256, GSM_TOTAL>>>(nullptr, 1, wih1, bih1, bhh1, Hdim);
    lstm_rec_kernel<1><<<Bsz / 2, 256>>>(whh1, nullptr, nullptr, nullptr);
    // Layer 2 + fused FC head
    gemm_mma_kernel<<<gblocks, 256, GSM_TOTAL>>>(nullptr, 2, wih2, bih2, bhh2, Hdim);
    lstm_rec_kernel<2><<<Bsz / 2, 256>>>(whh2, fcw, fcb, out);
}

// round 9
// speedup vs baseline: 1.1319x; 1.0903x over previous
#include <cuda_runtime.h>
#include <cuda_bf16.h>
#include <cstdint>

#define Bsz  256
#define Tlen 2048
#define Idim 128
#define Hdim 64
#define Gdim 256                       // 4*H
#define Mrows (Bsz * Tlen)             // 524288

// Scratch (static device arrays: allocation-free per harness rules)
__device__ float g_pre[(size_t)Mrows * Gdim];   // 512 MiB: pre-activations
__device__ float g_h0 [(size_t)Mrows * Hdim];   // 128 MiB: layer output ping
__device__ float g_h1 [(size_t)Mrows * Hdim];   // 128 MiB: layer output pong

__device__ __forceinline__ float sigm_f(float x) {
    return 1.0f / (1.0f + __expf(-x));
}
__device__ __forceinline__ float tanh_f(float x) {
    return 2.0f / (1.0f + __expf(-2.0f * x)) - 1.0f;
}

// ---------------------------------------------------------------------------
// mma.sync helpers (baseline PTX — works on plain sm_103 target)
// ---------------------------------------------------------------------------
__device__ __forceinline__ void ldsm_x4(uint32_t* r, uint32_t addr) {
    asm volatile("ldmatrix.sync.aligned.m8n8.x4.shared.b16 {%0,%1,%2,%3}, [%4];"
                 : "=r"(r[0]), "=r"(r[1]), "=r"(r[2]), "=r"(r[3]) : "r"(addr));
}
__device__ __forceinline__ void mma16816(float* d, const uint32_t* a, const uint32_t* b) {
    asm volatile(
        "mma.sync.aligned.m16n8k16.row.col.f32.bf16.bf16.f32 "
        "{%0,%1,%2,%3}, {%4,%5,%6,%7}, {%8,%9}, {%0,%1,%2,%3};"
        : "+f"(d[0]), "+f"(d[1]), "+f"(d[2]), "+f"(d[3])
        : "r"(a[0]), "r"(a[1]), "r"(a[2]), "r"(a[3]), "r"(b[0]), "r"(b[1]));
}

// ===========================================================================
// GEMM: g_pre[m, n] = sum_k A[m,k]*W[n,k] + bih[n] + bhh[n]
// Block tile M=64 x N=256 (full N), K-chunks of 32, split-bf16 3-term.
// (unchanged from round 8 — measured ~0.9 ms total for 3 layers)
// ===========================================================================
#define SMA_HI 0
#define SMA_LO 5120
#define SMW_HI 10240
#define SMW_LO 30720
#define GSM_TOTAL 51200

__global__ __launch_bounds__(256, 2) void gemm_mma_kernel(
    const float* __restrict__ Aext, int sel,
    const float* __restrict__ W,
    const float* __restrict__ bih, const float* __restrict__ bhh,
    int K)
{
    extern __shared__ char smem[];
    const uint32_t sbase = (uint32_t)__cvta_generic_to_shared(smem);

    const float* A = (sel == 0) ? Aext : ((sel == 1) ? g_h0 : g_h1);

    const int t   = threadIdx.x;
    const int wid = t >> 5;
    const int lid = t & 31;
    const int wm  = wid >> 2;          // 0..1 : warp row   (32 M each)
    const int wn  = wid & 3;           // 0..3 : warp col   (64 N each)
    const size_t m0 = (size_t)blockIdx.x * 64;

    float acc[2][8][4];
#pragma unroll
    for (int i = 0; i < 2; i++)
#pragma unroll
        for (int j = 0; j < 8; j++)
#pragma unroll
            for (int v = 0; v < 4; v++) acc[i][j][v] = 0.0f;

    // per-lane ldmatrix address components (stride 40 bf16 = 80B per row)
    const int rowA = wm * 32 + (lid & 7) + ((lid >> 3) & 1) * 8;
    const int colA = (lid >> 4) * 8;
    const int rowB = wn * 64 + (lid >> 4) * 8 + (lid & 7);
    const int colB = ((lid >> 3) & 1) * 8;

    const int nchunks = K >> 5;
    for (int c = 0; c < nchunks; c++) {
        const int k0 = c << 5;

        // ---- load + split-convert A tile (64 x 32): 512 float4, 2/thread ----
#pragma unroll
        for (int i = 0; i < 2; i++) {
            int f   = t + i * 256;
            int row = f >> 3;
            int c4  = (f & 7) << 2;
            float4 v = *(const float4*)&A[(m0 + row) * K + k0 + c4];
            __nv_bfloat162 h0 = __floats2bfloat162_rn(v.x, v.y);
            __nv_bfloat162 h1 = __floats2bfloat162_rn(v.z, v.w);
            __nv_bfloat162 l0 = __floats2bfloat162_rn(v.x - __bfloat162float(h0.x),
                                                      v.y - __bfloat162float(h0.y));
            __nv_bfloat162 l1 = __floats2bfloat162_rn(v.z - __bfloat162float(h1.x),
                                                      v.w - __bfloat162float(h1.y));
            uint32_t off = (uint32_t)(row * 40 + c4) * 2;
            *(uint2*)(smem + SMA_HI + off) =
                make_uint2(*(uint32_t*)&h0, *(uint32_t*)&h1);
            *(uint2*)(smem + SMA_LO + off) =
                make_uint2(*(uint32_t*)&l0, *(uint32_t*)&l1);
        }
        // ---- load + split-convert W tile (256 x 32): 2048 float4, 8/thread ----
#pragma unroll
        for (int i = 0; i < 8; i++) {
            int f   = t + i * 256;
            int row = f >> 3;
            int c4  = (f & 7) << 2;
            float4 v = *(const float4*)&W[(size_t)row * K + k0 + c4];
            __nv_bfloat162 h0 = __floats2bfloat162_rn(v.x, v.y);
            __nv_bfloat162 h1 = __floats2bfloat162_rn(v.z, v.w);
            __nv_bfloat162 l0 = __floats2bfloat162_rn(v.x - __bfloat162float(h0.x),
                                                      v.y - __bfloat162float(h0.y));
            __nv_bfloat162 l1 = __floats2bfloat162_rn(v.z - __bfloat162float(h1.x),
                                                      v.w - __bfloat162float(h1.y));
            uint32_t off = (uint32_t)(row * 40 + c4) * 2;
            *(uint2*)(smem + SMW_HI + off) =
                make_uint2(*(uint32_t*)&h0, *(uint32_t*)&h1);
            *(uint2*)(smem + SMW_LO + off) =
                make_uint2(*(uint32_t*)&l0, *(uint32_t*)&l1);
        }
        __syncthreads();

        // ---- mma over the 32-deep chunk (2 k16 steps, 3 precision terms) ----
#pragma unroll
        for (int kt = 0; kt < 2; kt++) {
            uint32_t afh[2][4], afl[2][4];
#pragma unroll
            for (int mt = 0; mt < 2; mt++) {
                uint32_t ao = (uint32_t)((rowA + mt * 16) * 40 + colA + kt * 16) * 2;
                ldsm_x4(afh[mt], sbase + SMA_HI + ao);
                ldsm_x4(afl[mt], sbase + SMA_LO + ao);
            }
#pragma unroll
            for (int nt2 = 0; nt2 < 4; nt2++) {
                uint32_t bo = (uint32_t)((rowB + nt2 * 16) * 40 + colB + kt * 16) * 2;
                uint32_t bfh[4], bfl[4];
                ldsm_x4(bfh, sbase + SMW_HI + bo);
                ldsm_x4(bfl, sbase + SMW_LO + bo);
#pragma unroll
                for (int mt = 0; mt < 2; mt++)
#pragma unroll
                    for (int half = 0; half < 2; half++) {
                        int nt = nt2 * 2 + half;
                        mma16816(acc[mt][nt], afh[mt], &bfh[half * 2]);  // hi*hi
                        mma16816(acc[mt][nt], afh[mt], &bfl[half * 2]);  // hi*lo
                        mma16816(acc[mt][nt], afl[mt], &bfh[half * 2]);  // lo*hi
                    }
            }
        }
        __syncthreads();
    }

    // ---- epilogue: d[row, n] + bias ----
    const int g  = lid >> 2;
    const int tg = lid & 3;
#pragma unroll
    for (int nt = 0; nt < 8; nt++) {
        int n = wn * 64 + nt * 8 + tg * 2;
        float b0 = bih[n]     + bhh[n];
        float b1 = bih[n + 1] + bhh[n + 1];
        size_t row0 = m0 + wm * 32 + g;
#pragma unroll
        for (int mt = 0; mt < 2; mt++) {
            size_t r0 = row0 + mt * 16;
            float2 o0 = make_float2(acc[mt][nt][0] + b0, acc[mt][nt][1] + b1);
            float2 o1 = make_float2(acc[mt][nt][2] + b0, acc[mt][nt][3] + b1);
            *(float2*)&g_pre[r0 * Gdim + n]       = o0;
            *(float2*)&g_pre[(r0 + 8) * Gdim + n] = o1;
        }
    }
}

// ===========================================================================
// Recurrent layer: one block per TWO batch elements, 512 threads
// (two independent 256-thread groups, one batch each -> 16 warps/SM for
// latency hiding; thread = one (batch, gate) pair, w_hh row in 64 regs).
// MODE 0 -> g_h0; MODE 1 -> g_h1; MODE 2 -> fused FC head into out.
// ===========================================================================
template <int MODE>
__global__ __launch_bounds__(512) void lstm_rec_kernel(
    const float* __restrict__ w_hh,
    const float* __restrict__ fc_w, const float* __restrict__ fc_b,
    float* __restrict__ out)
{
    __shared__ __align__(16) float h_s[2][64];
    __shared__ float gate_s[2][256];

    const int tid = threadIdx.x;
    const int bb  = tid >> 8;            // batch group 0/1
    const int gg  = tid & 255;           // gate index within group
    const int b2  = blockIdx.x;          // handles batches 2*b2, 2*b2+1
    const int batch = 2 * b2 + bb;

    float wreg[64];
#pragma unroll
    for (int k = 0; k < 64; k++) wreg[k] = w_hh[(size_t)gg * 64 + k];

    float c = 0.0f;                      // cell state (threads gg<64 use it)
    if (gg < 64) h_s[bb][gg] = 0.0f;

    float fwa = 0.0f, fwb = 0.0f, fcb = 0.0f;
    if (MODE == 2 && gg < 32) {
        fwa = fc_w[gg];
        fwb = fc_w[gg + 32];
        fcb = fc_b[0];
    }
    __syncthreads();

    const float* pre = g_pre + ((size_t)batch * Tlen) * Gdim + gg;
    float* hout = (MODE == 0) ? g_h0 : g_h1;

    float pn = pre[0];

    for (int t = 0; t < Tlen; t++) {
        float pv = pn;
        if (t + 1 < Tlen) pn = pre[(size_t)(t + 1) * Gdim];   // prefetch

        // gate pre-activation: pv + sum_k h[k] * w_hh[gg][k]
        float a0 = 0.0f, a1 = 0.0f, a2 = 0.0f, a3 = 0.0f;
        const float4* h4 = (const float4*)h_s[bb];
#pragma unroll
        for (int q = 0; q < 16; q++) {
            float4 hv = h4[q];
            a0 += wreg[4 * q + 0] * hv.x;
            a1 += wreg[4 * q + 1] * hv.y;
            a2 += wreg[4 * q + 2] * hv.z;
            a3 += wreg[4 * q + 3] * hv.w;
        }
        float s = pv + ((a0 + a1) + (a2 + a3));

        // i:[0,64) f:[64,128) g:[128,192) o:[192,256)  (warp-uniform branch)
        float v = (gg < 128 || gg >= 192) ? sigm_f(s) : tanh_f(s);
        gate_s[bb][gg] = v;
        __syncthreads();

        if (gg < 64) {
            float iv = gate_s[bb][gg];
            float fv = gate_s[bb][64 + gg];
            float gv = gate_s[bb][128 + gg];
            float ov = gate_s[bb][192 + gg];
            c = fv * c + iv * gv;
            float h = ov * tanh_f(c);
            h_s[bb][gg] = h;
            if (MODE < 2)
                hout[((size_t)batch * Tlen + t) * Hdim + gg] = h;
        }
        __syncthreads();

        if (MODE == 2 && gg < 32) {      // warp 0 of each group -> FC head
            float sfc = h_s[bb][gg] * fwa + h_s[bb][gg + 32] * fwb;
            sfc += __shfl_down_sync(0xffffffffu, sfc, 16);
            sfc += __shfl_down_sync(0xffffffffu, sfc, 8);
            sfc += __shfl_down_sync(0xffffffffu, sfc, 4);
            sfc += __shfl_down_sync(0xffffffffu, sfc, 2);
            sfc += __shfl_down_sync(0xffffffffu, sfc, 1);
            if (gg == 0) out[(size_t)batch * Tlen + t] = sfc + fcb;
        }
    }
}

extern "C" void kernel_launch(void* const* d_in, const int* in_sizes, int n_in,
                              void* d_out, int out_size)
{
    const float* x    = (const float*)d_in[0];
    const float* wih0 = (const float*)d_in[1];
    const float* whh0 = (const float*)d_in[2];
    const float* bih0 = (const float*)d_in[3];
    const float* bhh0 = (const float*)d_in[4];
    const float* wih1 = (const float*)d_in[5];
    const float* whh1 = (const float*)d_in[6];
    const float* bih1 = (const float*)d_in[7];
    const float* bhh1 = (const float*)d_in[8];
    const float* wih2 = (const float*)d_in[9];
    const float* whh2 = (const float*)d_in[10];
    const float* bih2 = (const float*)d_in[11];
    const float* bhh2 = (const float*)d_in[12];
    const float* fcw  = (const float*)d_in[13];
    const float* fcb  = (const float*)d_in[14];
    float* out = (float*)d_out;

    cudaFuncSetAttribute(gemm_mma_kernel,
                         cudaFuncAttributeMaxDynamicSharedMemorySize, GSM_TOTAL);

    const int gblocks = Mrows / 64;     // 8192

    // Layer 0
    gemm_mma_kernel<<<gblocks, 256, GSM_TOTAL>>>(x, 0, wih0, bih0, bhh0, Idim);
    lstm_rec_kernel<0><<<Bsz / 2, 512>>>(whh0, nullptr, nullptr, nullptr);
    // Layer 1
    gemm_mma_kernel<<<gblocks, 256, GSM_TOTAL>>>(nullptr, 1, wih1, bih1, bhh1, Hdim);
    lstm_rec_kernel<1><<<Bsz / 2, 512>>>(whh1, nullptr, nullptr, nullptr);
    // Layer 2 + fused FC head
    gemm_mma_kernel<<<gblocks, 256, GSM_TOTAL>>>(nullptr, 2, wih2, bih2, bhh2, Hdim);
    lstm_rec_kernel<2><<<Bsz / 2, 512>>>(whh2, fcw, fcb, out);
}